// round 15
// baseline (speedup 1.0000x reference)
#include <cuda_runtime.h>
#include <cuda_fp16.h>
#include <cstdint>

namespace {
constexpr float SCALE = 0.17677669529663687f;                 // 32^-0.5
constexpr float LOG2E = 1.4426950408889634f;
// per-buffer smem layout (fp16 rows: 40 elems = 80 B; stride-80 ldmatrix
// 8-row sets cover all 32 banks -> conflict-free, proven R8-R14)
constexpr int QS  = 0;                    // [256][40] fp16
constexpr int KS  = 20480;                // [256][40] fp16
constexpr int VS  = 40960;                // [256][40] fp16
constexpr int WT  = 61440;                // [9][32] fp32
constexpr int BSO = 62592;                // [32] fp32
constexpr int BUF = 62720;                // buffer stride
constexpr int SMEM_SZ = 2 * BUF;          // 125440 B -> 1 CTA/SM
}

// fp16 windowed scratch, attn-smem-image layout: [s][(tile*256+t)*40]
__device__ __align__(16) unsigned short g_half[3][(size_t)262144 * 40];
__device__ __align__(16) unsigned short g_oh[8388608];   // out windowed fp16

__device__ __forceinline__ uint32_t pkhf(float lo, float hi) {
    uint32_t r;
    asm("cvt.rn.f16x2.f32 %0, %1, %2;" : "=r"(r) : "f"(hi), "f"(lo));
    return r;
}
__device__ __forceinline__ float ex2f(float x) {
    float r;
    asm("ex2.approx.f32 %0, %1;" : "=f"(r) : "f"(x));
    return r;
}
__device__ __forceinline__ void ldsm4(uint32_t& r0, uint32_t& r1, uint32_t& r2, uint32_t& r3, uint32_t a) {
    asm volatile("ldmatrix.sync.aligned.m8n8.x4.shared.b16 {%0,%1,%2,%3}, [%4];"
        : "=r"(r0), "=r"(r1), "=r"(r2), "=r"(r3) : "r"(a));
}
__device__ __forceinline__ void ldsm4t(uint32_t& r0, uint32_t& r1, uint32_t& r2, uint32_t& r3, uint32_t a) {
    asm volatile("ldmatrix.sync.aligned.m8n8.x4.trans.shared.b16 {%0,%1,%2,%3}, [%4];"
        : "=r"(r0), "=r"(r1), "=r"(r2), "=r"(r3) : "r"(a));
}
__device__ __forceinline__ void mma16816(float* d, const uint32_t* a, uint32_t b0, uint32_t b1) {
    asm volatile("mma.sync.aligned.m16n8k16.row.col.f32.f16.f16.f32 "
        "{%0,%1,%2,%3}, {%4,%5,%6,%7}, {%8,%9}, {%0,%1,%2,%3};"
        : "+f"(d[0]), "+f"(d[1]), "+f"(d[2]), "+f"(d[3])
        : "r"(a[0]), "r"(a[1]), "r"(a[2]), "r"(a[3]), "r"(b0), "r"(b1));
}
__device__ __forceinline__ void cpa16(uint32_t dst, const void* src) {
    asm volatile("cp.async.cg.shared.global [%0], [%1], 16;" :: "r"(dst), "l"(src));
}
__device__ __forceinline__ void cpa4(uint32_t dst, const void* src) {
    asm volatile("cp.async.ca.shared.global [%0], [%1], 4;" :: "r"(dst), "l"(src));
}
#define CPA_COMMIT() asm volatile("cp.async.commit_group;" ::: "memory")
#define CPA_WAIT(n)  asm volatile("cp.async.wait_group %0;" :: "n"(n) : "memory")

// ---------------------------------------------------------------------------
// Kernel 1: repack temp (B,3,C,H,W) fp32 -> fp16 windowed scratch.
// Q pre-scaled by 32^-0.5 * log2(e).
// ---------------------------------------------------------------------------
__global__ void __launch_bounds__(256) repack_kernel(const float* __restrict__ temp) {
    __shared__ float tile[64 * 33];
    int r = blockIdx.x;
    int h = r & 63; r >>= 6;
    int head = r & 7; r >>= 3;
    int s = r % 3, b = r / 3;
    int tid = threadIdx.x;
    const float* src = temp + ((size_t)((b * 3 + s) * 256 + head * 32)) * 4096 + h * 64;
    int c = tid >> 3, w0 = (tid & 7) * 8;
    const float4* p = (const float4*)(src + (size_t)c * 4096 + w0);
    float4 v0 = p[0], v1 = p[1];
    float vv[8] = {v0.x, v0.y, v0.z, v0.w, v1.x, v1.y, v1.z, v1.w};
#pragma unroll
    for (int j = 0; j < 8; j++) tile[(w0 + j) * 33 + c] = vv[j];
    __syncthreads();
    int w = tid >> 2, c8 = (tid & 3) * 8;
    float o[8];
#pragma unroll
    for (int j = 0; j < 8; j++) o[j] = tile[w * 33 + c8 + j];
    int ww = w & 15, wsp = w >> 4;
    int win = b * 16 + ww, t = h * 4 + wsp;
    float m = (s == 0) ? SCALE * LOG2E : 1.0f;
    uint32_t pk[4];
#pragma unroll
    for (int j = 0; j < 4; j++) pk[j] = pkhf(o[2 * j] * m, o[2 * j + 1] * m);
    unsigned short* row = &g_half[s][((size_t)(win * 8 + head) * 256 + t) * 40];
    *(uint4*)(row + c8) = make_uint4(pk[0], pk[1], pk[2], pk[3]);
}

// stage one (win,head) tile into smem buffer sb (512 threads cooperate)
__device__ __forceinline__ void stage_tile(uint32_t sb, int tile, int tid,
                                           const float* __restrict__ gw,
                                           const float* __restrict__ gb) {
    size_t off = (size_t)tile * 256 * 40;
    const char* Qp = (const char*)&g_half[0][off];
    const char* Kp = (const char*)&g_half[1][off];
    const char* Vp = (const char*)&g_half[2][off];
    for (int i = tid; i < 1280; i += 512) {
        cpa16(sb + QS + i * 16, Qp + (size_t)i * 16);
        cpa16(sb + KS + i * 16, Kp + (size_t)i * 16);
        cpa16(sb + VS + i * 16, Vp + (size_t)i * 16);
    }
    int head = tile & 7;
    if (tid < 288) cpa4(sb + WT + tid * 4, gw + (head * 32 + (tid & 31)) * 9 + (tid >> 5));
    if (tid < 32) cpa4(sb + BSO + tid * 4, gb + head * 32 + tid);
}

// ---------------------------------------------------------------------------
// Kernel 2: persistent fp16 HMMA attention + lepe. 148 CTAs x 512 thr
// (16 warps, 1 CTA/SM). Each CTA loops ~7 (win,head) tiles; tile i+1 is
// cp.async-prefetched into the alternate buffer while tile i computes.
// Warp owns 16 query rows. exp = ex2.approx.f32 on fp32 accumulators.
// ---------------------------------------------------------------------------
__global__ void __launch_bounds__(512, 1) attn_mma(const float* __restrict__ gw,
                                                   const float* __restrict__ gb) {
    extern __shared__ char sm8[];
    uint32_t smb = (uint32_t)__cvta_generic_to_shared(sm8);
    int tid = threadIdx.x, lane = tid & 31, warp = tid >> 5;
    int bid = blockIdx.x;

    stage_tile(smb, bid, tid, gw, gb);
    CPA_COMMIT();

    int cur = 0;
    for (int tt = bid; tt < 1024; tt += 148) {
        uint32_t sb = smb + cur * BUF;
        char* sbp = sm8 + cur * BUF;
        CPA_WAIT(0);
        __syncthreads();                  // buffer cur ready; prior compute done
        int nt = tt + 148;
        if (nt < 1024) stage_tile(smb + (cur ^ 1) * BUF, nt, tid, gw, gb);
        CPA_COMMIT();

        float* Wt = (float*)(sbp + WT);
        float* Bs = (float*)(sbp + BSO);

        // Q fragments (16 rows per warp)
        int q0 = warp * 16;
        uint32_t qf[2][4];
#pragma unroll
        for (int kc = 0; kc < 2; kc++) {
            uint32_t a = sb + QS + (uint32_t)(q0 + (lane & 7) + ((lane >> 3) & 1) * 8) * 80
                       + (uint32_t)(kc * 16 + (lane >> 4) * 8) * 2;
            ldsm4(qf[kc][0], qf[kc][1], qf[kc][2], qf[kc][3], a);
        }

        float O[4][4];
#pragma unroll
        for (int nj = 0; nj < 4; nj++) O[nj][0] = O[nj][1] = O[nj][2] = O[nj][3] = 0.f;
        float lr0 = 0.f, lr1 = 0.f;

#pragma unroll
        for (int kb = 0; kb < 4; kb++) {
            int keyb = kb * 64;
            uint32_t ap[4][4];
#pragma unroll
            for (int j = 0; j < 8; j++) {
                uint32_t ka = sb + KS + (uint32_t)(keyb + j * 8 + (lane & 7)) * 80
                            + (uint32_t)((lane >> 3) * 8) * 2;
                uint32_t r0, r1, r2, r3;
                ldsm4(r0, r1, r2, r3, ka);
                float a4[4] = {0.f, 0.f, 0.f, 0.f};
                mma16816(a4, qf[0], r0, r1);
                mma16816(a4, qf[1], r2, r3);
                float e0 = ex2f(a4[0]), e1 = ex2f(a4[1]);
                float e2 = ex2f(a4[2]), e3 = ex2f(a4[3]);
                lr0 += e0 + e1;
                lr1 += e2 + e3;
                ap[j >> 1][(j & 1) * 2]     = pkhf(e0, e1);
                ap[j >> 1][(j & 1) * 2 + 1] = pkhf(e2, e3);
            }
#pragma unroll
            for (int nj = 0; nj < 4; nj++) {
#pragma unroll
                for (int cp = 0; cp < 2; cp++) {
                    uint32_t va = sb + VS + (uint32_t)(keyb + cp * 32 + lane) * 80
                                + (uint32_t)(nj * 8) * 2;
                    uint32_t r0, r1, r2, r3;
                    ldsm4t(r0, r1, r2, r3, va);
                    mma16816(O[nj], ap[2 * cp],     r0, r1);
                    mma16816(O[nj], ap[2 * cp + 1], r2, r3);
                }
            }
        }

        // epilogue: normalize + lepe (fp16 v), store windowed fp16
        float l0 = lr0, l1 = lr1;
        l0 += __shfl_xor_sync(0xffffffffu, l0, 1);
        l0 += __shfl_xor_sync(0xffffffffu, l0, 2);
        l1 += __shfl_xor_sync(0xffffffffu, l1, 1);
        l1 += __shfl_xor_sync(0xffffffffu, l1, 2);
        float inv0 = 1.0f / l0, inv1 = 1.0f / l1;
        int r = lane >> 2, cp2 = (lane & 3) * 2;
        int t0 = q0 + r, t1 = t0 + 8;
        size_t obase = (size_t)tt * (256 * 32);
#pragma unroll
        for (int nj = 0; nj < 4; nj++) {
            int d = nj * 8 + cp2;
#pragma unroll
            for (int q = 0; q < 2; q++) {
                int t = q ? t1 : t0;
                int h = t >> 2, ws = t & 3;
                float ax = Bs[d], ay = Bs[d + 1];
#pragma unroll
                for (int kh = 0; kh < 3; kh++) {
                    int hn = h + kh - 1;
                    if ((unsigned)hn < 64u) {
#pragma unroll
                        for (int kw = 0; kw < 3; kw++) {
                            int wn = ws + kw - 1;
                            if ((unsigned)wn < 4u) {
                                int tn = hn * 4 + wn;
                                uint32_t vp = *(const uint32_t*)(sbp + VS + tn * 80 + d * 2);
                                float vx = __half2float(__ushort_as_half((unsigned short)vp));
                                float vy = __half2float(__ushort_as_half((unsigned short)(vp >> 16)));
                                float2 wg = *(const float2*)(Wt + (kh * 3 + kw) * 32 + d);
                                ax = fmaf(vx, wg.x, ax);
                                ay = fmaf(vy, wg.y, ay);
                            }
                        }
                    }
                }
                float inv = q ? inv1 : inv0;
                *(uint32_t*)(g_oh + obase + (size_t)t * 32 + d) =
                    pkhf(fmaf(O[nj][q * 2], inv, ax), fmaf(O[nj][q * 2 + 1], inv, ay));
            }
        }
        cur ^= 1;
    }
}

// Kernel 3: inverse repack g_oh (fp16 windowed) -> out (B,C,H,W) fp32.
__global__ void __launch_bounds__(256) unpack_kernel(float* __restrict__ out) {
    __shared__ float tile[64 * 33];
    int r = blockIdx.x;
    int h = r & 63; r >>= 6;
    int head = r & 7, b = r >> 3;
    int tid = threadIdx.x;
    int w = tid >> 2, c8 = (tid & 3) * 8;
    int ww = w & 15, wsp = w >> 4;
    int win = b * 16 + ww, t = h * 4 + wsp;
    const unsigned short* src = g_oh + ((size_t)(win * 8 + head) * 256 + t) * 32 + c8;
    uint4 a = *(const uint4*)src;
    uint32_t u[4] = {a.x, a.y, a.z, a.w};
#pragma unroll
    for (int j = 0; j < 4; j++) {
        tile[w * 33 + c8 + 2 * j]     = __half2float(__ushort_as_half((unsigned short)u[j]));
        tile[w * 33 + c8 + 2 * j + 1] = __half2float(__ushort_as_half((unsigned short)(u[j] >> 16)));
    }
    __syncthreads();
    int c = tid >> 3, w0 = (tid & 7) * 8;
    float o[8];
#pragma unroll
    for (int j = 0; j < 8; j++) o[j] = tile[(w0 + j) * 33 + c];
    float* dst = out + ((size_t)(b * 256 + head * 32 + c)) * 4096 + h * 64 + w0;
    ((float4*)dst)[0] = make_float4(o[0], o[1], o[2], o[3]);
    ((float4*)dst)[1] = make_float4(o[4], o[5], o[6], o[7]);
}

extern "C" void kernel_launch(void* const* d_in, const int* in_sizes, int n_in,
                              void* d_out, int out_size) {
    const float* temp = (const float*)d_in[0];
    const float* gw = (const float*)d_in[1];
    const float* gb = (const float*)d_in[2];
    float* out = (float*)d_out;
    (void)in_sizes; (void)n_in; (void)out_size;

    cudaFuncSetAttribute(attn_mma, cudaFuncAttributeMaxDynamicSharedMemorySize, SMEM_SZ);
    repack_kernel<<<12288, 256>>>(temp);
    attn_mma<<<148, 512, SMEM_SZ>>>(gw, gb);
    unpack_kernel<<<4096, 256>>>(out);
}

// round 16
// speedup vs baseline: 1.0713x; 1.0713x over previous
#include <cuda_runtime.h>
#include <cuda_fp16.h>
#include <cstdint>

namespace {
constexpr float SCALE = 0.17677669529663687f;                 // 32^-0.5
constexpr float LOG2E = 1.4426950408889634f;
// attn smem. fp16 rows: 40 elems = 80 B. 8-row ldmatrix sets at stride 80 B
// hit word offsets {0,20,8,28,16,4,24,12}*4B -> all 32 banks, 0 conflicts.
constexpr int QS  = 0;                    // [256][40] fp16
constexpr int KS  = 20480;                // [256][40] fp16
constexpr int VS  = 40960;                // [256][40] fp16
constexpr int WT  = 61440;                // [9][32] fp32
constexpr int BSO = 62592;                // [32] fp32
constexpr int SMEM_SZ = 62720;            // 2 CTAs/SM
}

// fp16 windowed scratch, attn-smem-image layout: [s][((win*8+head)*256+t)*40]
__device__ __align__(16) unsigned short g_half[3][(size_t)262144 * 40];
__device__ __align__(16) unsigned short g_oh[8388608];   // out windowed fp16

__device__ __forceinline__ uint32_t pkhf(float lo, float hi) {
    uint32_t r;
    asm("cvt.rn.f16x2.f32 %0, %1, %2;" : "=r"(r) : "f"(hi), "f"(lo));
    return r;
}
__device__ __forceinline__ float ex2f(float x) {
    float r;
    asm("ex2.approx.f32 %0, %1;" : "=f"(r) : "f"(x));
    return r;
}
__device__ __forceinline__ void ldsm4(uint32_t& r0, uint32_t& r1, uint32_t& r2, uint32_t& r3, uint32_t a) {
    asm volatile("ldmatrix.sync.aligned.m8n8.x4.shared.b16 {%0,%1,%2,%3}, [%4];"
        : "=r"(r0), "=r"(r1), "=r"(r2), "=r"(r3) : "r"(a));
}
__device__ __forceinline__ void ldsm4t(uint32_t& r0, uint32_t& r1, uint32_t& r2, uint32_t& r3, uint32_t a) {
    asm volatile("ldmatrix.sync.aligned.m8n8.x4.trans.shared.b16 {%0,%1,%2,%3}, [%4];"
        : "=r"(r0), "=r"(r1), "=r"(r2), "=r"(r3) : "r"(a));
}
__device__ __forceinline__ void mma16816(float* d, const uint32_t* a, uint32_t b0, uint32_t b1) {
    asm volatile("mma.sync.aligned.m16n8k16.row.col.f32.f16.f16.f32 "
        "{%0,%1,%2,%3}, {%4,%5,%6,%7}, {%8,%9}, {%0,%1,%2,%3};"
        : "+f"(d[0]), "+f"(d[1]), "+f"(d[2]), "+f"(d[3])
        : "r"(a[0]), "r"(a[1]), "r"(a[2]), "r"(a[3]), "r"(b0), "r"(b1));
}
__device__ __forceinline__ void cpa16(uint32_t dst, const void* src) {
    asm volatile("cp.async.cg.shared.global [%0], [%1], 16;" :: "r"(dst), "l"(src));
}
__device__ __forceinline__ void cpa4(uint32_t dst, const void* src) {
    asm volatile("cp.async.ca.shared.global [%0], [%1], 4;" :: "r"(dst), "l"(src));
}
#define CPA_COMMIT() asm volatile("cp.async.commit_group;" ::: "memory")
#define CPA_WAIT(n)  asm volatile("cp.async.wait_group %0;" :: "n"(n) : "memory")

// ---------------------------------------------------------------------------
// Kernel 1: repack temp (B,3,C,H,W) fp32 -> fp16 windowed scratch.
// Q pre-scaled by 32^-0.5 * log2(e).
// ---------------------------------------------------------------------------
__global__ void __launch_bounds__(256) repack_kernel(const float* __restrict__ temp) {
    __shared__ float tile[64 * 33];
    int r = blockIdx.x;
    int h = r & 63; r >>= 6;
    int head = r & 7; r >>= 3;
    int s = r % 3, b = r / 3;
    int tid = threadIdx.x;
    const float* src = temp + ((size_t)((b * 3 + s) * 256 + head * 32)) * 4096 + h * 64;
    int c = tid >> 3, w0 = (tid & 7) * 8;
    const float4* p = (const float4*)(src + (size_t)c * 4096 + w0);
    float4 v0 = p[0], v1 = p[1];
    float vv[8] = {v0.x, v0.y, v0.z, v0.w, v1.x, v1.y, v1.z, v1.w};
#pragma unroll
    for (int j = 0; j < 8; j++) tile[(w0 + j) * 33 + c] = vv[j];
    __syncthreads();
    int w = tid >> 2, c8 = (tid & 3) * 8;
    float o[8];
#pragma unroll
    for (int j = 0; j < 8; j++) o[j] = tile[w * 33 + c8 + j];
    int ww = w & 15, wsp = w >> 4;
    int win = b * 16 + ww, t = h * 4 + wsp;
    float m = (s == 0) ? SCALE * LOG2E : 1.0f;
    uint32_t pk[4];
#pragma unroll
    for (int j = 0; j < 4; j++) pk[j] = pkhf(o[2 * j] * m, o[2 * j + 1] * m);
    unsigned short* row = &g_half[s][((size_t)(win * 8 + head) * 256 + t) * 40];
    *(uint4*)(row + c8) = make_uint4(pk[0], pk[1], pk[2], pk[3]);
}

// ---------------------------------------------------------------------------
// Kernel 2: fp16 HMMA attention + lepe. CTA = (win,head), 256 thr / 8 warps,
// 2 CTAs/SM (R14-proven structure). All Q/K/V resident; exp = ex2.approx.f32
// on fp32 accumulators (log2e pre-folded into Q); fp32 register row sums;
// K frags shared across both row blocks. Output stored windowed fp16.
// ---------------------------------------------------------------------------
__global__ void __launch_bounds__(256, 2) attn_mma(const float* __restrict__ gw,
                                                   const float* __restrict__ gb) {
    extern __shared__ char sm8[];
    uint32_t smb = (uint32_t)__cvta_generic_to_shared(sm8);
    float* Wt = (float*)(sm8 + WT);
    float* Bs = (float*)(sm8 + BSO);

    int tid = threadIdx.x, lane = tid & 31, warp = tid >> 5;
    int bid = blockIdx.x;
    int ww = bid & 15, head = (bid >> 4) & 7, b = bid >> 7;
    int win = b * 16 + ww;

    const char* Qp = (const char*)&g_half[0][(size_t)(win * 8 + head) * 256 * 40];
    const char* Kp = (const char*)&g_half[1][(size_t)(win * 8 + head) * 256 * 40];
    const char* Vp = (const char*)&g_half[2][(size_t)(win * 8 + head) * 256 * 40];

    // prologue: stage everything, one wait.
#pragma unroll
    for (int it = 0; it < 5; it++) {
        int i = it * 256 + tid;
        cpa16(smb + QS + i * 16, Qp + i * 16);
        cpa16(smb + KS + i * 16, Kp + i * 16);
        cpa16(smb + VS + i * 16, Vp + i * 16);
    }
    for (int i = tid; i < 288; i += 256) cpa4(smb + WT + i * 4, gw + (head * 32 + (i & 31)) * 9 + (i >> 5));
    if (tid < 32) cpa4(smb + BSO + tid * 4, gb + head * 32 + tid);
    CPA_COMMIT();
    CPA_WAIT(0);
    __syncthreads();     // only block barrier in the kernel

    // hoisted Q fragments: [rb][kc][4]
    uint32_t qf[2][2][4];
#pragma unroll
    for (int rb = 0; rb < 2; rb++)
#pragma unroll
        for (int kc = 0; kc < 2; kc++) {
            uint32_t a = smb + QS
                + (uint32_t)(warp * 32 + rb * 16 + (lane & 7) + ((lane >> 3) & 1) * 8) * 80
                + (uint32_t)(kc * 16 + (lane >> 4) * 8) * 2;
            ldsm4(qf[rb][kc][0], qf[rb][kc][1], qf[rb][kc][2], qf[rb][kc][3], a);
        }

    float O[2][4][4];
#pragma unroll
    for (int rb = 0; rb < 2; rb++)
#pragma unroll
        for (int nj = 0; nj < 4; nj++) O[rb][nj][0] = O[rb][nj][1] = O[rb][nj][2] = O[rb][nj][3] = 0.f;
    float lr[2][2] = {{0.f, 0.f}, {0.f, 0.f}};

#pragma unroll
    for (int kb = 0; kb < 4; kb++) {
        int keyb = kb * 64;
        uint32_t ap[2][4][4];
#pragma unroll
        for (int j = 0; j < 8; j++) {
            uint32_t ka = smb + KS + (uint32_t)(keyb + j * 8 + (lane & 7)) * 80
                        + (uint32_t)((lane >> 3) * 8) * 2;
            uint32_t r0, r1, r2, r3;
            ldsm4(r0, r1, r2, r3, ka);       // K frags shared by both rb
#pragma unroll
            for (int rb = 0; rb < 2; rb++) {
                float a4[4] = {0.f, 0.f, 0.f, 0.f};
                mma16816(a4, qf[rb][0], r0, r1);
                mma16816(a4, qf[rb][1], r2, r3);
                float e0 = ex2f(a4[0]), e1 = ex2f(a4[1]);
                float e2 = ex2f(a4[2]), e3 = ex2f(a4[3]);
                lr[rb][0] += e0 + e1;
                lr[rb][1] += e2 + e3;
                ap[rb][j >> 1][(j & 1) * 2]     = pkhf(e0, e1);
                ap[rb][j >> 1][(j & 1) * 2 + 1] = pkhf(e2, e3);
            }
        }
        // O += P V (V frags shared by both row blocks)
#pragma unroll
        for (int nj = 0; nj < 4; nj++) {
#pragma unroll
            for (int cp = 0; cp < 2; cp++) {
                uint32_t va = smb + VS + (uint32_t)(keyb + cp * 32 + lane) * 80 + (uint32_t)(nj * 8) * 2;
                uint32_t r0, r1, r2, r3;
                ldsm4t(r0, r1, r2, r3, va);
                mma16816(O[0][nj], ap[0][2 * cp],     r0, r1);
                mma16816(O[0][nj], ap[0][2 * cp + 1], r2, r3);
                mma16816(O[1][nj], ap[1][2 * cp],     r0, r1);
                mma16816(O[1][nj], ap[1][2 * cp + 1], r2, r3);
            }
        }
    }

    // epilogue: normalize + lepe (fp16 v), store windowed fp16
    size_t obase = (size_t)(win * 8 + head) * (256 * 32);
#pragma unroll
    for (int rb = 0; rb < 2; rb++) {
        float l0 = lr[rb][0], l1 = lr[rb][1];
        l0 += __shfl_xor_sync(0xffffffffu, l0, 1);
        l0 += __shfl_xor_sync(0xffffffffu, l0, 2);
        l1 += __shfl_xor_sync(0xffffffffu, l1, 1);
        l1 += __shfl_xor_sync(0xffffffffu, l1, 2);
        float inv0 = 1.0f / l0, inv1 = 1.0f / l1;
        int q0 = warp * 32 + rb * 16;
        int r = lane >> 2, cp2 = (lane & 3) * 2;
        int t0 = q0 + r, t1 = t0 + 8;
#pragma unroll
        for (int nj = 0; nj < 4; nj++) {
            int d = nj * 8 + cp2;
#pragma unroll
            for (int q = 0; q < 2; q++) {
                int t = q ? t1 : t0;
                int h = t >> 2, ws = t & 3;
                float ax = Bs[d], ay = Bs[d + 1];
#pragma unroll
                for (int kh = 0; kh < 3; kh++) {
                    int hn = h + kh - 1;
                    if ((unsigned)hn < 64u) {
#pragma unroll
                        for (int kw = 0; kw < 3; kw++) {
                            int wn = ws + kw - 1;
                            if ((unsigned)wn < 4u) {
                                int tn = hn * 4 + wn;
                                uint32_t vp = *(const uint32_t*)(sm8 + VS + tn * 80 + d * 2);
                                float vx = __half2float(__ushort_as_half((unsigned short)vp));
                                float vy = __half2float(__ushort_as_half((unsigned short)(vp >> 16)));
                                float2 wg = *(const float2*)(Wt + (kh * 3 + kw) * 32 + d);
                                ax = fmaf(vx, wg.x, ax);
                                ay = fmaf(vy, wg.y, ay);
                            }
                        }
                    }
                }
                float inv = q ? inv1 : inv0;
                *(uint32_t*)(g_oh + obase + (size_t)t * 32 + d) =
                    pkhf(fmaf(O[rb][nj][q * 2], inv, ax), fmaf(O[rb][nj][q * 2 + 1], inv, ay));
            }
        }
    }
}

// Kernel 3: inverse repack g_oh (fp16 windowed) -> out (B,C,H,W) fp32.
__global__ void __launch_bounds__(256) unpack_kernel(float* __restrict__ out) {
    __shared__ float tile[64 * 33];
    int r = blockIdx.x;
    int h = r & 63; r >>= 6;
    int head = r & 7, b = r >> 3;
    int tid = threadIdx.x;
    int w = tid >> 2, c8 = (tid & 3) * 8;
    int ww = w & 15, wsp = w >> 4;
    int win = b * 16 + ww, t = h * 4 + wsp;
    const unsigned short* src = g_oh + ((size_t)(win * 8 + head) * 256 + t) * 32 + c8;
    uint4 a = *(const uint4*)src;
    uint32_t u[4] = {a.x, a.y, a.z, a.w};
#pragma unroll
    for (int j = 0; j < 4; j++) {
        tile[w * 33 + c8 + 2 * j]     = __half2float(__ushort_as_half((unsigned short)u[j]));
        tile[w * 33 + c8 + 2 * j + 1] = __half2float(__ushort_as_half((unsigned short)(u[j] >> 16)));
    }
    __syncthreads();
    int c = tid >> 3, w0 = (tid & 7) * 8;
    float o[8];
#pragma unroll
    for (int j = 0; j < 8; j++) o[j] = tile[(w0 + j) * 33 + c];
    float* dst = out + ((size_t)(b * 256 + head * 32 + c)) * 4096 + h * 64 + w0;
    ((float4*)dst)[0] = make_float4(o[0], o[1], o[2], o[3]);
    ((float4*)dst)[1] = make_float4(o[4], o[5], o[6], o[7]);
}

extern "C" void kernel_launch(void* const* d_in, const int* in_sizes, int n_in,
                              void* d_out, int out_size) {
    const float* temp = (const float*)d_in[0];
    const float* gw = (const float*)d_in[1];
    const float* gb = (const float*)d_in[2];
    float* out = (float*)d_out;
    (void)in_sizes; (void)n_in; (void)out_size;

    cudaFuncSetAttribute(attn_mma, cudaFuncAttributeMaxDynamicSharedMemorySize, SMEM_SZ);
    repack_kernel<<<12288, 256>>>(temp);
    attn_mma<<<1024, 256, SMEM_SZ>>>(gw, gb);
    unpack_kernel<<<4096, 256>>>(out);
}